// round 4
// baseline (speedup 1.0000x reference)
#include <cuda_runtime.h>
#include <cuda_bf16.h>
#include <cstdint>

// Output = one_hot(arange(N), N) @ W = I @ W = W: an 8 MiB D2D copy.
//
// R1 (grid-stride LDG), R2 (CE memcpy), R3 (MLP4 LDG.128) all land at
// 5.9-6.9us (~2.8 TB/s combined) with every ncu counter idle (DRAM 18%,
// L2 15%, issue 3%). LDG-stream shaping is irrelevant. This round tests
// the one remaining request path: TMA bulk copy (cp.async.bulk / UBLKCP),
// which generates bursts from the TMA engine instead of the LSU/L1tex
// wavefront path. 256 CTAs x 32 KiB, double-buffered 2x16 KiB:
// load[0], load[1] in flight together; store[s] as mbar[s] flips.

static constexpr int STAGE_BYTES = 16384;          // 16 KiB per stage
static constexpr int NUM_STAGES  = 2;              // 32 KiB per CTA
static constexpr int CHUNK_BYTES = STAGE_BYTES * NUM_STAGES;

__device__ __forceinline__ uint32_t smem_u32(const void* p) {
    return (uint32_t)__cvta_generic_to_shared(p);
}

__global__ void __launch_bounds__(32) tma_copy_kernel(const char* __restrict__ src,
                                                      char* __restrict__ dst) {
    __shared__ alignas(128) char buf[NUM_STAGES][STAGE_BYTES];
    __shared__ alignas(8) uint64_t mbar[NUM_STAGES];

    if (threadIdx.x == 0) {
        const char* g_src = src + (size_t)blockIdx.x * CHUNK_BYTES;
        char*       g_dst = dst + (size_t)blockIdx.x * CHUNK_BYTES;

        // Init mbarriers (arrive count 1 each).
        #pragma unroll
        for (int s = 0; s < NUM_STAGES; s++) {
            uint32_t mb = smem_u32(&mbar[s]);
            asm volatile("mbarrier.init.shared.b64 [%0], 1;" :: "r"(mb) : "memory");
        }
        asm volatile("fence.proxy.async.shared::cta;" ::: "memory");

        // Fire both bulk loads (both in flight simultaneously).
        #pragma unroll
        for (int s = 0; s < NUM_STAGES; s++) {
            uint32_t mb = smem_u32(&mbar[s]);
            uint32_t sd = smem_u32(&buf[s][0]);
            asm volatile("mbarrier.arrive.expect_tx.shared.b64 _, [%0], %1;"
                         :: "r"(mb), "r"((uint32_t)STAGE_BYTES) : "memory");
            asm volatile(
                "cp.async.bulk.shared::cta.global.mbarrier::complete_tx::bytes "
                "[%0], [%1], %2, [%3];"
                :: "r"(sd), "l"(g_src + s * STAGE_BYTES),
                   "r"((uint32_t)STAGE_BYTES), "r"(mb) : "memory");
        }

        // As each stage lands, bulk-store it back out.
        #pragma unroll
        for (int s = 0; s < NUM_STAGES; s++) {
            uint32_t mb = smem_u32(&mbar[s]);
            // Wait for load completion (phase 0).
            asm volatile(
                "{\n\t"
                ".reg .pred P;\n\t"
                "WAIT_%=:\n\t"
                "mbarrier.try_wait.parity.shared.b64 P, [%0], 0;\n\t"
                "@!P bra WAIT_%=;\n\t"
                "}"
                :: "r"(mb) : "memory");
            uint32_t sd = smem_u32(&buf[s][0]);
            asm volatile(
                "cp.async.bulk.global.shared::cta.bulk_group [%0], [%1], %2;"
                :: "l"(g_dst + s * STAGE_BYTES), "r"(sd),
                   "r"((uint32_t)STAGE_BYTES) : "memory");
        }
        asm volatile("cp.async.bulk.commit_group;" ::: "memory");
        asm volatile("cp.async.bulk.wait_group 0;" ::: "memory");
    }
}

extern "C" void kernel_launch(void* const* d_in, const int* in_sizes, int n_in,
                              void* d_out, int out_size) {
    const char* W = (const char*)d_in[0];
    char* out = (char*)d_out;
    // Total bytes = 16384*128*4 = 8388608; / 32768 per CTA = 256 CTAs exact.
    int blocks = (int)(((size_t)out_size * sizeof(float)) / CHUNK_BYTES);
    tma_copy_kernel<<<blocks, 32>>>(W, out);
}